// round 16
// baseline (speedup 1.0000x reference)
#include <cuda_runtime.h>
#include <cuda_fp16.h>

#define NN 50000
#define EE 250000
#define TT 4
#define ROWS (TT*NN)
#define ETOT (TT*EE)
#define CHUNK 1024
#define NBLK ((ROWS + CHUNK - 1) / CHUNK)   // 196
#define NG23 ((NN + 511) / 512)             // 98
#define EG512 ((ETOT + 511) / 512)          // 1954
#define DSBLK ((ROWS + 511) / 512)          // 391 (resident-grid safe)

// ---------------- scratch (static device globals) ----------------
__device__ float  d_el[ROWS * 2];
__device__ float  d_er[ROWS * 2];
__device__ float  d_wal[3 * 512];
__device__ float  d_war[3 * 512];
__device__ __half d_aggh[(size_t)ROWS * 128];
__device__ __half d_hbuf[2 * (size_t)NN * 64];
__device__ __half d_wt0[TT * 128 * 24];
__device__ __half d_wt1[TT * 128 * 64];
__device__ float  d_msum[TT * 128];
__device__ int    d_deg[ROWS];
__device__ int    d_rowptr[ROWS + 1];
__device__ int    d_cursor[ROWS];
__device__ int    d_csrc[ETOT];
__device__ int    d_bsum[NBLK];
__device__ int    d_scanflag[NBLK];
__device__ int    d_scandone;
__device__ int    d_rowperm[ROWS];
__device__ int    d_bucket[64];
__device__ int    d_bcursor[64];
__device__ int    d_gs1, d_gs2;
__device__ int    d_ctr;

__device__ __forceinline__ float lrelu(float x) { return x > 0.f ? x : 0.2f * x; }
__device__ __forceinline__ float ex2f(float x) {
    float r;
    asm("ex2.approx.f32 %0, %1;" : "=f"(r) : "f"(x));
    return r;
}
// el/er are prescaled by log2(e); w = ex2(max(s, 0.2s)) == exp(lrelu(el+er))
__device__ __forceinline__ float wexp(float s) { return ex2f(fmaxf(s, 0.2f * s)); }

#define MMA16816(d, a, b0_, b1_) \
    asm volatile("mma.sync.aligned.m16n8k16.row.col.f32.f16.f16.f32 " \
        "{%0,%1,%2,%3}, {%4,%5,%6,%7}, {%8,%9}, {%0,%1,%2,%3};" \
        : "+f"((d)[0]), "+f"((d)[1]), "+f"((d)[2]), "+f"((d)[3]) \
        : "r"((a)[0]), "r"((a)[1]), "r"((a)[2]), "r"((a)[3]), \
          "r"(b0_), "r"(b1_))

// ========== prep ==========
__global__ void prep_kernel(const float* __restrict__ W0, const float* __restrict__ al0, const float* __restrict__ ar0,
                            const float* __restrict__ W1, const float* __restrict__ al1, const float* __restrict__ ar1,
                            const float* __restrict__ W2, const float* __restrict__ al2, const float* __restrict__ ar2) {
    int gi = blockIdx.x * blockDim.x + threadIdx.x;
    int stride = gridDim.x * blockDim.x;
    for (int j = gi; j < ROWS; j += stride) d_deg[j] = 0;
    if (gi < TT * 128) d_msum[gi] = 0.f;
    if (gi < NBLK) d_scanflag[gi] = 0;
    if (gi < 64) { d_bucket[gi] = 0; d_bcursor[gi] = 0; }
    if (gi == 0) { d_ctr = 0; d_scandone = 0; d_gs1 = 0; d_gs2 = 0; }

    for (int i = gi; i < TT * 128 * 24; i += stride) {
        int t = i / (128 * 24);
        int r = i - t * 128 * 24;
        int n = r / 24, k = r - n * 24;
        float v = (k < 23) ? W0[((size_t)(t * 23 + k)) * 128 + n] : 0.f;
        d_wt0[i] = __float2half(v);
    }
    for (int i = gi; i < TT * 128 * 64; i += stride) {
        int t = i / (128 * 64);
        int r = i - t * 128 * 64;
        int n = r / 64, k = r - n * 64;
        d_wt1[i] = __float2half(W1[((size_t)(t * 64 + k)) * 128 + n]);
    }

    if (blockIdx.x < 3) {
        int L = blockIdx.x;
        const float* W  = (L == 0) ? W0  : (L == 1) ? W1  : W2;
        const float* al = (L == 0) ? al0 : (L == 1) ? al1 : al2;
        const float* ar = (L == 0) ? ar0 : (L == 1) ? ar1 : ar2;
        int K = (L == 0) ? 23 : 64;
        const float LOG2E = 1.4426950408889634f;
        for (int idx = threadIdx.x; idx < TT * 2 * K; idx += blockDim.x) {
            int t = idx / (2 * K);
            int rem = idx - t * 2 * K;
            int hh = rem / K;
            int k = rem - hh * K;
            float sl = 0.f, sr = 0.f;
            const float* Wr = W + ((size_t)(t * K + k)) * 128 + hh * 64;
            const float* alr = al + (t * 2 + hh) * 64;
            const float* arr = ar + (t * 2 + hh) * 64;
#pragma unroll
            for (int j = 0; j < 64; j++) {
                float w = Wr[j];
                sl = fmaf(w, alr[j], sl);
                sr = fmaf(w, arr[j], sr);
            }
            d_wal[L * 512 + (t * 2 + hh) * 64 + k] = sl * LOG2E;   // prescale
            d_war[L * 512 + (t * 2 + hh) * 64 + k] = sr * LOG2E;
        }
    }
}

__global__ void hist_kernel(const int* __restrict__ edges) {
    int i = blockIdx.x * blockDim.x + threadIdx.x;
    if (i >= ETOT) return;
    int t = i / EE, e = i - t * EE;
    int d = edges[(size_t)t * 2 * EE + EE + e];
    atomicAdd(&d_deg[t * NN + d], 1);
}

// ===== fused: lookback scan + eler23 + scatter (as R15) =====
__global__ void scanscat_eler_kernel(const int* __restrict__ edges,
                                     const float* __restrict__ x) {
    int tid = threadIdx.x;
    if (blockIdx.x < NBLK) {
        __shared__ int sm[512];
        __shared__ int sp[512];
        int b = blockIdx.x;
        int base = b * CHUNK + tid * 2;
        int v0 = (base < ROWS) ? d_deg[base] : 0;
        int v1 = (base + 1 < ROWS) ? d_deg[base + 1] : 0;
        sm[tid] = v0 + v1;
        __syncthreads();
        for (int o = 1; o < 512; o <<= 1) {
            int add = (tid >= o) ? sm[tid - o] : 0;
            __syncthreads();
            sm[tid] += add;
            __syncthreads();
        }
        if (tid == 0) {
            d_bsum[b] = sm[511];
            __threadfence();
            atomicExch(&d_scanflag[b], 1);
        }
        int myv = 0;
        if (tid < b) {
            while (atomicAdd(&d_scanflag[tid], 0) == 0) {}
            __threadfence();
            myv = d_bsum[tid];
        }
        sp[tid] = myv;
        __syncthreads();
        for (int o = 256; o > 0; o >>= 1) {
            if (tid < o) sp[tid] += sp[tid + o];
            __syncthreads();
        }
        int pre = sp[0];
        int off = pre + (tid ? sm[tid - 1] : 0);
        if (base < ROWS)     { d_rowptr[base] = off;          d_cursor[base] = off; }
        if (base + 1 < ROWS) { d_rowptr[base + 1] = off + v0; d_cursor[base + 1] = off + v0; }
        if (b == 0 && tid == 0) d_rowptr[ROWS] = ETOT;
        __threadfence();
        __syncthreads();
        if (tid == 0) atomicAdd(&d_scandone, 1);
    } else if (blockIdx.x < NBLK + NG23) {
        __shared__ float swal[512], swar[512];
        swal[tid] = d_wal[tid];
        swar[tid] = d_war[tid];
        __syncthreads();
        int n = (blockIdx.x - NBLK) * 512 + tid;
        if (n >= NN) return;
        float hreg[23];
#pragma unroll
        for (int i = 0; i < 23; i++) hreg[i] = x[(size_t)n * 23 + i];
#pragma unroll
        for (int t = 0; t < TT; t++) {
            float pl0 = 0.f, pl1 = 0.f, pr0 = 0.f, pr1 = 0.f;
            int b0 = (t * 2) * 64, b1 = (t * 2 + 1) * 64;
#pragma unroll
            for (int k = 0; k < 23; k++) {
                float hk = hreg[k];
                pl0 = fmaf(hk, swal[b0 + k], pl0);
                pl1 = fmaf(hk, swal[b1 + k], pl1);
                pr0 = fmaf(hk, swar[b0 + k], pr0);
                pr1 = fmaf(hk, swar[b1 + k], pr1);
            }
            *(float2*)&d_el[((size_t)t * NN + n) * 2] = make_float2(pl0, pl1);
            *(float2*)&d_er[((size_t)t * NN + n) * 2] = make_float2(pr0, pr1);
        }
    } else {
        if (tid == 0) {
            while (atomicAdd(&d_scandone, 0) < NBLK) {}
        }
        __syncthreads();
        __threadfence();
        int i = (blockIdx.x - NBLK - NG23) * 512 + tid;
        if (i >= ETOT) return;
        int t = i / EE, e = i - t * EE;
        int s = edges[(size_t)t * 2 * EE + e];
        int d = edges[(size_t)t * 2 * EE + EE + e];
        int pos = atomicAdd(&d_cursor[t * NN + d], 1);
        d_csrc[pos] = s;
    }
}

// ===== degree counting-sort of rows (resident grid, 2 spin syncs) =====
__global__ void degsort_kernel() {
    int tid = threadIdx.x;
    int gi = blockIdx.x * 512 + tid;
    int b = 0;
    if (gi < ROWS) {
        int deg = d_rowptr[gi + 1] - d_rowptr[gi];
        b = min(deg, 63);
        atomicAdd(&d_bucket[b], 1);
    }
    __threadfence();
    __syncthreads();
    if (tid == 0) {
        atomicAdd(&d_gs1, 1);
        while (atomicAdd(&d_gs1, 0) < (int)gridDim.x) {}
    }
    __syncthreads();
    __threadfence();
    if (blockIdx.x == 0 && tid < 64) {
        int s = 0;
        for (int i = 0; i < tid; i++) s += d_bucket[i];
        d_bcursor[tid] = s;
    }
    __threadfence();
    __syncthreads();
    if (tid == 0) {
        atomicAdd(&d_gs2, 1);
        while (atomicAdd(&d_gs2, 0) < (int)gridDim.x) {}
    }
    __syncthreads();
    __threadfence();
    if (gi < ROWS) {
        int pos = atomicAdd(&d_bcursor[b], 1);
        d_rowperm[pos] = gi;
    }
}

// ================= eler (layers 1,2) =================
__global__ void eler64_kernel(const __half* __restrict__ h, int layer) {
    __shared__ float swal[512], swar[512];
    int tid = threadIdx.x;
    swal[tid] = d_wal[layer * 512 + tid];
    swar[tid] = d_war[layer * 512 + tid];
    __syncthreads();
    int n = blockIdx.x * blockDim.x + tid;
    if (n >= NN) return;
    float hreg[64];
    const __half2* hr = (const __half2*)(h + (size_t)n * 64);
#pragma unroll
    for (int i = 0; i < 32; i++) {
        float2 v = __half22float2(hr[i]);
        hreg[2 * i] = v.x;
        hreg[2 * i + 1] = v.y;
    }
#pragma unroll
    for (int t = 0; t < TT; t++) {
        float pl0 = 0.f, pl1 = 0.f, pr0 = 0.f, pr1 = 0.f;
        int b0 = (t * 2) * 64, b1 = (t * 2 + 1) * 64;
#pragma unroll
        for (int k = 0; k < 64; k++) {
            float hk = hreg[k];
            pl0 = fmaf(hk, swal[b0 + k], pl0);
            pl1 = fmaf(hk, swal[b1 + k], pl1);
            pr0 = fmaf(hk, swar[b0 + k], pr0);
            pr1 = fmaf(hk, swar[b1 + k], pr1);
        }
        *(float2*)&d_el[((size_t)t * NN + n) * 2] = make_float2(pl0, pl1);
        *(float2*)&d_er[((size_t)t * NN + n) * 2] = make_float2(pr0, pr1);
    }
}

// ================= segment =================
// layer 0 (fp32 x, K=23): warp-per-row, ex2 weights
__global__ void segment23_kernel(const float* __restrict__ x) {
    int tid = threadIdx.x;
    int lane = tid & 31;
    int row = (blockIdx.x * blockDim.x + tid) >> 5;
    if (row >= ROWS) return;
    int t = row / NN;
    const float* elb = d_el + (size_t)t * NN * 2;
    int beg = d_rowptr[row], end = d_rowptr[row + 1];
    float2 er2 = *(const float2*)&d_er[(size_t)row * 2];

    float den0 = 0.f, den1 = 0.f;
    float as0 = 0.f, as1 = 0.f;

    for (int j = beg; j < end; j += 2) {
        int sA = d_csrc[j];
        bool hasB = (j + 1 < end);
        int sB = hasB ? d_csrc[j + 1] : sA;
        float2 elA = *(const float2*)&elb[(size_t)sA * 2];
        float2 elB = *(const float2*)&elb[(size_t)sB * 2];
        float wA0 = wexp(elA.x + er2.x);
        float wA1 = wexp(elA.y + er2.y);
        float wB0 = hasB ? wexp(elB.x + er2.x) : 0.f;
        float wB1 = hasB ? wexp(elB.y + er2.y) : 0.f;
        den0 += wA0 + wB0;
        den1 += wA1 + wB1;
        float hA = (lane < 23) ? x[(size_t)sA * 23 + lane] : 0.f;
        float hB = (lane < 23) ? x[(size_t)sB * 23 + lane] : 0.f;
        as0 = fmaf(wA0, hA, fmaf(wB0, hB, as0));
        as1 = fmaf(wA1, hA, fmaf(wB1, hB, as1));
    }
    float inv0 = (end > beg) ? 1.f / den0 : 0.f;
    float inv1 = (end > beg) ? 1.f / den1 : 0.f;
    size_t base = (size_t)row * 48;
    if (lane < 23) {
        d_aggh[base + lane]      = __float2half(as0 * inv0);
        d_aggh[base + 24 + lane] = __float2half(as1 * inv1);
    } else if (lane == 23) {
        d_aggh[base + 23] = __float2half(0.f);
        d_aggh[base + 47] = __float2half(0.f);
    }
}

// layers 1,2 (fp16 h, K=64): TWO rows per warp (16 lanes each), deg-sorted
__global__ void segment64p_kernel(const __half* __restrict__ h) {
    int tid = threadIdx.x;
    int lane = tid & 31;
    int half = lane >> 4;      // row slot within warp
    int gl = lane & 15;        // lane within 16-lane group
    int widx = (blockIdx.x * blockDim.x + tid) >> 5;
    int ridx = widx * 2 + half;
    if (ridx >= ROWS) return;
    int row = d_rowperm[ridx];
    int t = row / NN;
    const float* elb = d_el + (size_t)t * NN * 2;
    const char* hb = (const char*)h;
    int beg = d_rowptr[row], end = d_rowptr[row + 1];
    float2 er2 = *(const float2*)&d_er[(size_t)row * 2];

    float den0 = 0.f, den1 = 0.f;
    float4 a0 = make_float4(0.f, 0.f, 0.f, 0.f);
    float4 a1 = make_float4(0.f, 0.f, 0.f, 0.f);

    for (int j = beg; j < end; j += 2) {
        int sA = d_csrc[j];
        bool hasB = (j + 1 < end);
        int sB = hasB ? d_csrc[j + 1] : sA;
        float2 elA = *(const float2*)&elb[(size_t)sA * 2];
        float2 elB = *(const float2*)&elb[(size_t)sB * 2];
        float wA0 = wexp(elA.x + er2.x);
        float wA1 = wexp(elA.y + er2.y);
        float wB0 = hasB ? wexp(elB.x + er2.x) : 0.f;
        float wB1 = hasB ? wexp(elB.y + er2.y) : 0.f;
        den0 += wA0 + wB0;
        den1 += wA1 + wB1;
        // each lane: 4 halves (8B) of the node's 128B row
        uint2 rA = *(const uint2*)(hb + ((size_t)sA * 128 + gl * 8));
        uint2 rB = *(const uint2*)(hb + ((size_t)sB * 128 + gl * 8));
        float2 hA0 = __half22float2(*(__half2*)&rA.x);
        float2 hA1 = __half22float2(*(__half2*)&rA.y);
        float2 hB0 = __half22float2(*(__half2*)&rB.x);
        float2 hB1 = __half22float2(*(__half2*)&rB.y);
        a0.x = fmaf(wA0, hA0.x, fmaf(wB0, hB0.x, a0.x));
        a0.y = fmaf(wA0, hA0.y, fmaf(wB0, hB0.y, a0.y));
        a0.z = fmaf(wA0, hA1.x, fmaf(wB0, hB1.x, a0.z));
        a0.w = fmaf(wA0, hA1.y, fmaf(wB0, hB1.y, a0.w));
        a1.x = fmaf(wA1, hA0.x, fmaf(wB1, hB0.x, a1.x));
        a1.y = fmaf(wA1, hA0.y, fmaf(wB1, hB0.y, a1.y));
        a1.z = fmaf(wA1, hA1.x, fmaf(wB1, hB1.x, a1.z));
        a1.w = fmaf(wA1, hA1.y, fmaf(wB1, hB1.y, a1.w));
    }
    float inv0 = (end > beg) ? 1.f / den0 : 0.f;
    float inv1 = (end > beg) ? 1.f / den1 : 0.f;
    __half2 p00 = __floats2half2_rn(a0.x * inv0, a0.y * inv0);
    __half2 p01 = __floats2half2_rn(a0.z * inv0, a0.w * inv0);
    __half2 p10 = __floats2half2_rn(a1.x * inv1, a1.y * inv1);
    __half2 p11 = __floats2half2_rn(a1.z * inv1, a1.w * inv1);
    uint2 o0, o1;
    o0.x = *(unsigned*)&p00; o0.y = *(unsigned*)&p01;
    o1.x = *(unsigned*)&p10; o1.y = *(unsigned*)&p11;
    *(uint2*)&d_aggh[(size_t)row * 128 + 4 * gl]      = o0;   // head0
    *(uint2*)&d_aggh[(size_t)row * 128 + 64 + 4 * gl] = o1;   // head1
}

// ===== out gemm 64 (layer 1): mma.sync m16n8k16 fp16 =====
__global__ void out_gemm64_kernel(const float* __restrict__ b,
                                  __half* __restrict__ hout) {
    constexpr int WS = 72;
    constexpr int AS = 136;
    __shared__ __align__(16) char sbuf[36864];
    __half* Ws = (__half*)sbuf;
    __half* As = (__half*)(sbuf + 128 * WS * 2);
    float*  St = (float*)sbuf;

    int tid = threadIdx.x;
    int warp = tid >> 5, lane = tid & 31;
    int g = lane >> 2, tg = lane & 3;
    int mrow = (warp & 3) * 16;
    int head = warp >> 2;
    int nbase = blockIdx.x * 64;
    int nvalid = min(64, NN - nbase);

    float acc[8][4];
#pragma unroll
    for (int i = 0; i < 8; i++)
#pragma unroll
        for (int j = 0; j < 4; j++) acc[i][j] = 0.f;

    for (int t = 0; t < TT; t++) {
        const uint4* wsrc = (const uint4*)(d_wt1 + (size_t)t * 128 * 64);
        for (int i = tid; i < 128 * 8; i += 256) {
            int row = i >> 3, c = i & 7;
            *(uint4*)&Ws[row * WS + c * 8] = wsrc[i];
        }
        const uint4* asrc = (const uint4*)(d_aggh + ((size_t)t * NN + nbase) * 128);
        for (int i = tid; i < nvalid * 16; i += 256) {
            int node = i >> 4, c = i & 15;
            *(uint4*)&As[node * AS + c * 8] = asrc[i];
        }
        __syncthreads();

        unsigned afr[4][4];
        const __half* Abase = As + (size_t)mrow * AS + head * 64;
#pragma unroll
        for (int k16 = 0; k16 < 4; k16++) {
            const __half* ab = Abase + k16 * 16;
            afr[k16][0] = *(const unsigned*)&ab[g * AS + tg * 2];
            afr[k16][1] = *(const unsigned*)&ab[(g + 8) * AS + tg * 2];
            afr[k16][2] = *(const unsigned*)&ab[g * AS + tg * 2 + 8];
            afr[k16][3] = *(const unsigned*)&ab[(g + 8) * AS + tg * 2 + 8];
        }
#pragma unroll
        for (int nt = 0; nt < 8; nt++) {
            const __half* wb = Ws + (size_t)(head * 64 + nt * 8 + g) * WS;
#pragma unroll
            for (int k16 = 0; k16 < 4; k16++) {
                unsigned b0 = *(const unsigned*)&wb[k16 * 16 + tg * 2];
                unsigned b1 = *(const unsigned*)&wb[k16 * 16 + tg * 2 + 8];
                MMA16816(acc[nt], afr[k16], b0, b1);
            }
        }
        __syncthreads();
    }

#pragma unroll
    for (int nt = 0; nt < 8; nt++) {
        int col = head * 64 + nt * 8 + tg * 2;
        St[(mrow + g) * 128 + col]     = acc[nt][0];
        St[(mrow + g) * 128 + col + 1] = acc[nt][1];
        St[(mrow + 8 + g) * 128 + col]     = acc[nt][2];
        St[(mrow + 8 + g) * 128 + col + 1] = acc[nt][3];
    }
    __syncthreads();

    int dd = tid & 63;
    int q = tid >> 6;
    float bm0 = 0.f, bm1 = 0.f;
#pragma unroll
    for (int t = 0; t < TT; t++) {
        bm0 += b[t * 128 + dd];
        bm1 += b[t * 128 + 64 + dd];
    }
    bm0 *= 0.25f; bm1 *= 0.25f;
#pragma unroll
    for (int i = 0; i < 16; i++) {
        int node = q * 16 + i;
        int n = nbase + node;
        if (n < NN) {
            float v0 = St[node * 128 + dd] * 0.25f + bm0;
            float v1 = St[node * 128 + 64 + dd] * 0.25f + bm1;
            v0 = fmaxf(v0, 0.f);
            v1 = fmaxf(v1, 0.f);
            float nrm = sqrtf(v0 * v0 + v1 * v1);
            float inv = 1.f / fmaxf(nrm, 1e-12f);
            hout[(size_t)n * 64 + dd] = __float2half(0.5f * (v0 + v1) * inv);
        }
    }
}

// ===== out gemm layer0 (K=23 -> padded 32): mma.sync =====
__global__ void out_gemm23_kernel(const float* __restrict__ b,
                                  __half* __restrict__ hout) {
    constexpr int WS = 40;
    constexpr int AS = 72;
    constexpr int HS = 32;
    __shared__ __align__(16) char sbuf[36864];
    __half* Ws = (__half*)sbuf;
    __half* As = (__half*)(sbuf + 128 * WS * 2);
    float*  St = (float*)sbuf;

    int tid = threadIdx.x;
    int warp = tid >> 5, lane = tid & 31;
    int g = lane >> 2, tg = lane & 3;
    int mrow = (warp & 3) * 16;
    int head = warp >> 2;
    int nbase = blockIdx.x * 64;
    int nvalid = min(64, NN - nbase);

    float acc[8][4];
#pragma unroll
    for (int i = 0; i < 8; i++)
#pragma unroll
        for (int j = 0; j < 4; j++) acc[i][j] = 0.f;

    for (int t = 0; t < TT; t++) {
        const uint4* wsrc = (const uint4*)(d_wt0 + (size_t)t * 128 * 24);
        for (int i = tid; i < 128 * 3; i += 256) {
            int row = i / 3, c = i - row * 3;
            *(uint4*)&Ws[row * WS + c * 8] = wsrc[i];
        }
        for (int i = tid; i < 128; i += 256) {
            uint4 z = make_uint4(0u, 0u, 0u, 0u);
            *(uint4*)&Ws[i * WS + 24] = z;
        }
        const __half* asrc = d_aggh + ((size_t)t * NN + nbase) * 48;
        for (int i = tid; i < nvalid * 64; i += 256) {
            int node = i >> 6, j = i & 63;
            int hh = j >> 5, k = j & 31;
            __half v = (k < 24) ? asrc[node * 48 + hh * 24 + k] : __float2half(0.f);
            As[node * AS + hh * HS + k] = v;
        }
        __syncthreads();

        unsigned afr[2][4];
        const __half* Abase = As + (size_t)mrow * AS + head * HS;
#pragma unroll
        for (int k16 = 0; k16 < 2; k16++) {
            const __half* ab = Abase + k16 * 16;
            afr[k16][0] = *(const unsigned*)&ab[g * AS + tg * 2];
            afr[k16][1] = *(const unsigned*)&ab[(g + 8) * AS + tg * 2];
            afr[k16][2] = *(const unsigned*)&ab[g * AS + tg * 2 + 8];
            afr[k16][3] = *(const unsigned*)&ab[(g + 8) * AS + tg * 2 + 8];
        }
#pragma unroll
        for (int nt = 0; nt < 8; nt++) {
            const __half* wb = Ws + (size_t)(head * 64 + nt * 8 + g) * WS;
#pragma unroll
            for (int k16 = 0; k16 < 2; k16++) {
                unsigned b0 = *(const unsigned*)&wb[k16 * 16 + tg * 2];
                unsigned b1 = *(const unsigned*)&wb[k16 * 16 + tg * 2 + 8];
                MMA16816(acc[nt], afr[k16], b0, b1);
            }
        }
        __syncthreads();
    }

#pragma unroll
    for (int nt = 0; nt < 8; nt++) {
        int col = head * 64 + nt * 8 + tg * 2;
        St[(mrow + g) * 128 + col]     = acc[nt][0];
        St[(mrow + g) * 128 + col + 1] = acc[nt][1];
        St[(mrow + 8 + g) * 128 + col]     = acc[nt][2];
        St[(mrow + 8 + g) * 128 + col + 1] = acc[nt][3];
    }
    __syncthreads();

    int dd = tid & 63;
    int q = tid >> 6;
    float bm0 = 0.f, bm1 = 0.f;
#pragma unroll
    for (int t = 0; t < TT; t++) {
        bm0 += b[t * 128 + dd];
        bm1 += b[t * 128 + 64 + dd];
    }
    bm0 *= 0.25f; bm1 *= 0.25f;
#pragma unroll
    for (int i = 0; i < 16; i++) {
        int node = q * 16 + i;
        int n = nbase + node;
        if (n < NN) {
            float v0 = St[node * 128 + dd] * 0.25f + bm0;
            float v1 = St[node * 128 + 64 + dd] * 0.25f + bm1;
            v0 = fmaxf(v0, 0.f);
            v1 = fmaxf(v1, 0.f);
            float nrm = sqrtf(v0 * v0 + v1 * v1);
            float inv = 1.f / fmaxf(nrm, 1e-12f);
            hout[(size_t)n * 64 + dd] = __float2half(0.5f * (v0 + v1) * inv);
        }
    }
}

// ==== layer 2 collapsed: node-mean of agg (half2 loads) + final GEMM ====
__global__ void aggmean_final_kernel(const float* __restrict__ W2,
                                     const float* __restrict__ b2,
                                     float* __restrict__ out) {
    int t = blockIdx.y;
    int c2 = threadIdx.x & 63;
    int sub = threadIdx.x >> 6;
    float2 s = make_float2(0.f, 0.f);
    for (int n = blockIdx.x * 2 + sub; n < NN; n += gridDim.x * 2) {
        __half2 v = *(const __half2*)&d_aggh[((size_t)t * NN + n) * 128 + 2 * c2];
        float2 f = __half22float2(v);
        s.x += f.x; s.y += f.y;
    }
    __shared__ float2 sr[128];
    sr[threadIdx.x] = s;
    __syncthreads();
    if (sub == 0) {
        float2 o = sr[c2];
        float2 o1 = sr[64 + c2];
        atomicAdd(&d_msum[t * 128 + 2 * c2],     o.x + o1.x);
        atomicAdd(&d_msum[t * 128 + 2 * c2 + 1], o.y + o1.y);
    }
    __threadfence();
    __syncthreads();
    __shared__ int flag;
    if (threadIdx.x == 0) {
        int v = atomicAdd(&d_ctr, 1);
        flag = (v == (int)(gridDim.x * gridDim.y) - 1);
    }
    __syncthreads();
    if (!flag) return;
    __threadfence();

    __shared__ float sm_m[512];
    for (int i = threadIdx.x; i < 512; i += 128) sm_m[i] = d_msum[i];
    __syncthreads();
    if (threadIdx.x < 64) {
        int dd = threadIdx.x;
        float sum = 0.f;
#pragma unroll
        for (int tt = 0; tt < TT; tt++)
#pragma unroll
            for (int hh = 0; hh < 2; hh++)
                for (int k = 0; k < 64; k++)
                    sum = fmaf(sm_m[tt * 128 + hh * 64 + k],
                               W2[((size_t)(tt * 64 + k)) * 128 + hh * 64 + dd], sum);
        sum *= 0.125f / (float)NN;
        float bb = 0.f;
#pragma unroll
        for (int tt = 0; tt < TT; tt++)
            bb += b2[tt * 128 + dd] + b2[tt * 128 + 64 + dd];
        out[dd] = sum + bb * 0.125f;
    }
}

// ================= driver =================
extern "C" void kernel_launch(void* const* d_in, const int* in_sizes, int n_in,
                              void* d_out, int out_size) {
    const float* x   = (const float*)d_in[0];
    const int* edges = (const int*)  d_in[1];
    const float* W0  = (const float*)d_in[2];
    const float* al0 = (const float*)d_in[3];
    const float* ar0 = (const float*)d_in[4];
    const float* b0  = (const float*)d_in[5];
    const float* W1  = (const float*)d_in[6];
    const float* al1 = (const float*)d_in[7];
    const float* ar1 = (const float*)d_in[8];
    const float* b1  = (const float*)d_in[9];
    const float* W2  = (const float*)d_in[10];
    const float* al2 = (const float*)d_in[11];
    const float* ar2 = (const float*)d_in[12];
    const float* b2  = (const float*)d_in[13];
    float* out = (float*)d_out;

    void* hptr = nullptr;
    cudaGetSymbolAddress(&hptr, d_hbuf);
    __half* h1 = (__half*)hptr;
    __half* h2 = h1 + (size_t)NN * 64;

    const int eg = (ETOT + 511) / 512;
    const int ng = (NN + 511) / 512;
    const int sg = (ROWS * 32 + 511) / 512;       // segment23: warp per row
    const int sgp = (ROWS / 2 * 32 + 511) / 512;  // segment64p: warp per 2 rows (6250)
    const int gg = (NN + 63) / 64;

    prep_kernel<<<256, 256>>>(W0, al0, ar0, W1, al1, ar1, W2, al2, ar2);
    hist_kernel<<<eg, 512>>>(edges);
    scanscat_eler_kernel<<<NBLK + NG23 + EG512, 512>>>(edges, x);
    degsort_kernel<<<DSBLK, 512>>>();

    // ---- layer 0 ----
    segment23_kernel<<<sg, 512>>>(x);
    out_gemm23_kernel<<<gg, 256>>>(b0, h1);

    // ---- layer 1 ----
    eler64_kernel<<<ng, 512>>>(h1, 1);
    segment64p_kernel<<<sgp, 512>>>(h1);
    out_gemm64_kernel<<<gg, 256>>>(b1, h2);

    // ---- layer 2 (collapsed output) ----
    eler64_kernel<<<ng, 512>>>(h2, 2);
    segment64p_kernel<<<sgp, 512>>>(h2);
    {
        dim3 ag(512, TT);
        aggmean_final_kernel<<<ag, 128>>>(W2, b2, out);
    }
}

// round 17
// speedup vs baseline: 1.2033x; 1.2033x over previous
#include <cuda_runtime.h>
#include <cuda_fp16.h>

#define NN 50000
#define EE 250000
#define TT 4
#define ROWS (TT*NN)
#define ETOT (TT*EE)
#define CHUNK 1024
#define NBLK ((ROWS + CHUNK - 1) / CHUNK)   // 196
#define NG23 ((NN + 511) / 512)             // 98
#define EG512 ((ETOT + 511) / 512)          // 1954

// ---------------- scratch (static device globals) ----------------
__device__ float  d_el[ROWS * 2];
__device__ float  d_er[ROWS * 2];
__device__ float  d_wal[3 * 512];
__device__ float  d_war[3 * 512];
__device__ __half d_aggh[(size_t)ROWS * 128];
__device__ __half d_hbuf[2 * (size_t)NN * 64];
__device__ __half d_wt0[TT * 128 * 24];
__device__ __half d_wt1[TT * 128 * 64];
__device__ float  d_msum[TT * 128];
__device__ int    d_deg[ROWS];
__device__ int    d_rowptr[ROWS + 1];
__device__ int    d_cursor[ROWS];
__device__ int    d_csrc[ETOT];
__device__ int    d_bsum[NBLK];
__device__ int    d_scanflag[NBLK];
__device__ int    d_scandone;
__device__ int    d_ctr;

__device__ __forceinline__ float ex2f(float x) {
    float r;
    asm("ex2.approx.f32 %0, %1;" : "=f"(r) : "f"(x));
    return r;
}
// el/er are prescaled by log2(e); w = ex2(max(s, 0.2s)) == exp(lrelu(el+er))
__device__ __forceinline__ float wexp(float s) { return ex2f(fmaxf(s, 0.2f * s)); }

#define MMA16816(d, a, b0_, b1_) \
    asm volatile("mma.sync.aligned.m16n8k16.row.col.f32.f16.f16.f32 " \
        "{%0,%1,%2,%3}, {%4,%5,%6,%7}, {%8,%9}, {%0,%1,%2,%3};" \
        : "+f"((d)[0]), "+f"((d)[1]), "+f"((d)[2]), "+f"((d)[3]) \
        : "r"((a)[0]), "r"((a)[1]), "r"((a)[2]), "r"((a)[3]), \
          "r"(b0_), "r"(b1_))

// ========== prep ==========
__global__ void prep_kernel(const float* __restrict__ W0, const float* __restrict__ al0, const float* __restrict__ ar0,
                            const float* __restrict__ W1, const float* __restrict__ al1, const float* __restrict__ ar1,
                            const float* __restrict__ W2, const float* __restrict__ al2, const float* __restrict__ ar2) {
    int gi = blockIdx.x * blockDim.x + threadIdx.x;
    int stride = gridDim.x * blockDim.x;
    for (int j = gi; j < ROWS; j += stride) d_deg[j] = 0;
    if (gi < TT * 128) d_msum[gi] = 0.f;
    if (gi < NBLK) d_scanflag[gi] = 0;
    if (gi == 0) { d_ctr = 0; d_scandone = 0; }

    for (int i = gi; i < TT * 128 * 24; i += stride) {
        int t = i / (128 * 24);
        int r = i - t * 128 * 24;
        int n = r / 24, k = r - n * 24;
        float v = (k < 23) ? W0[((size_t)(t * 23 + k)) * 128 + n] : 0.f;
        d_wt0[i] = __float2half(v);
    }
    for (int i = gi; i < TT * 128 * 64; i += stride) {
        int t = i / (128 * 64);
        int r = i - t * 128 * 64;
        int n = r / 64, k = r - n * 64;
        d_wt1[i] = __float2half(W1[((size_t)(t * 64 + k)) * 128 + n]);
    }

    if (blockIdx.x < 3) {
        int L = blockIdx.x;
        const float* W  = (L == 0) ? W0  : (L == 1) ? W1  : W2;
        const float* al = (L == 0) ? al0 : (L == 1) ? al1 : al2;
        const float* ar = (L == 0) ? ar0 : (L == 1) ? ar1 : ar2;
        int K = (L == 0) ? 23 : 64;
        const float LOG2E = 1.4426950408889634f;
        for (int idx = threadIdx.x; idx < TT * 2 * K; idx += blockDim.x) {
            int t = idx / (2 * K);
            int rem = idx - t * 2 * K;
            int hh = rem / K;
            int k = rem - hh * K;
            float sl = 0.f, sr = 0.f;
            const float* Wr = W + ((size_t)(t * K + k)) * 128 + hh * 64;
            const float* alr = al + (t * 2 + hh) * 64;
            const float* arr = ar + (t * 2 + hh) * 64;
#pragma unroll
            for (int j = 0; j < 64; j++) {
                float w = Wr[j];
                sl = fmaf(w, alr[j], sl);
                sr = fmaf(w, arr[j], sr);
            }
            d_wal[L * 512 + (t * 2 + hh) * 64 + k] = sl * LOG2E;   // prescale
            d_war[L * 512 + (t * 2 + hh) * 64 + k] = sr * LOG2E;
        }
    }
}

__global__ void hist_kernel(const int* __restrict__ edges) {
    int i = blockIdx.x * blockDim.x + threadIdx.x;
    if (i >= ETOT) return;
    int t = i / EE, e = i - t * EE;
    int d = edges[(size_t)t * 2 * EE + EE + e];
    atomicAdd(&d_deg[t * NN + d], 1);
}

// ===== fused: lookback scan + eler23 + scatter =====
__global__ void scanscat_eler_kernel(const int* __restrict__ edges,
                                     const float* __restrict__ x) {
    int tid = threadIdx.x;
    if (blockIdx.x < NBLK) {
        __shared__ int sm[512];
        __shared__ int sp[512];
        int b = blockIdx.x;
        int base = b * CHUNK + tid * 2;
        int v0 = (base < ROWS) ? d_deg[base] : 0;
        int v1 = (base + 1 < ROWS) ? d_deg[base + 1] : 0;
        sm[tid] = v0 + v1;
        __syncthreads();
        for (int o = 1; o < 512; o <<= 1) {
            int add = (tid >= o) ? sm[tid - o] : 0;
            __syncthreads();
            sm[tid] += add;
            __syncthreads();
        }
        if (tid == 0) {
            d_bsum[b] = sm[511];
            __threadfence();
            atomicExch(&d_scanflag[b], 1);
        }
        int myv = 0;
        if (tid < b) {
            while (atomicAdd(&d_scanflag[tid], 0) == 0) {}
            __threadfence();
            myv = d_bsum[tid];
        }
        sp[tid] = myv;
        __syncthreads();
        for (int o = 256; o > 0; o >>= 1) {
            if (tid < o) sp[tid] += sp[tid + o];
            __syncthreads();
        }
        int pre = sp[0];
        int off = pre + (tid ? sm[tid - 1] : 0);
        if (base < ROWS)     { d_rowptr[base] = off;          d_cursor[base] = off; }
        if (base + 1 < ROWS) { d_rowptr[base + 1] = off + v0; d_cursor[base + 1] = off + v0; }
        if (b == 0 && tid == 0) d_rowptr[ROWS] = ETOT;
        __threadfence();
        __syncthreads();
        if (tid == 0) atomicAdd(&d_scandone, 1);
    } else if (blockIdx.x < NBLK + NG23) {
        __shared__ float swal[512], swar[512];
        swal[tid] = d_wal[tid];
        swar[tid] = d_war[tid];
        __syncthreads();
        int n = (blockIdx.x - NBLK) * 512 + tid;
        if (n >= NN) return;
        float hreg[23];
#pragma unroll
        for (int i = 0; i < 23; i++) hreg[i] = x[(size_t)n * 23 + i];
#pragma unroll
        for (int t = 0; t < TT; t++) {
            float pl0 = 0.f, pl1 = 0.f, pr0 = 0.f, pr1 = 0.f;
            int b0 = (t * 2) * 64, b1 = (t * 2 + 1) * 64;
#pragma unroll
            for (int k = 0; k < 23; k++) {
                float hk = hreg[k];
                pl0 = fmaf(hk, swal[b0 + k], pl0);
                pl1 = fmaf(hk, swal[b1 + k], pl1);
                pr0 = fmaf(hk, swar[b0 + k], pr0);
                pr1 = fmaf(hk, swar[b1 + k], pr1);
            }
            *(float2*)&d_el[((size_t)t * NN + n) * 2] = make_float2(pl0, pl1);
            *(float2*)&d_er[((size_t)t * NN + n) * 2] = make_float2(pr0, pr1);
        }
    } else {
        if (tid == 0) {
            while (atomicAdd(&d_scandone, 0) < NBLK) {}
        }
        __syncthreads();
        __threadfence();
        int i = (blockIdx.x - NBLK - NG23) * 512 + tid;
        if (i >= ETOT) return;
        int t = i / EE, e = i - t * EE;
        int s = edges[(size_t)t * 2 * EE + e];
        int d = edges[(size_t)t * 2 * EE + EE + e];
        int pos = atomicAdd(&d_cursor[t * NN + d], 1);
        d_csrc[pos] = s;
    }
}

// ================= eler (layers 1,2) =================
__global__ void eler64_kernel(const __half* __restrict__ h, int layer) {
    __shared__ float swal[512], swar[512];
    int tid = threadIdx.x;
    swal[tid] = d_wal[layer * 512 + tid];
    swar[tid] = d_war[layer * 512 + tid];
    __syncthreads();
    int n = blockIdx.x * blockDim.x + tid;
    if (n >= NN) return;
    float hreg[64];
    const __half2* hr = (const __half2*)(h + (size_t)n * 64);
#pragma unroll
    for (int i = 0; i < 32; i++) {
        float2 v = __half22float2(hr[i]);
        hreg[2 * i] = v.x;
        hreg[2 * i + 1] = v.y;
    }
#pragma unroll
    for (int t = 0; t < TT; t++) {
        float pl0 = 0.f, pl1 = 0.f, pr0 = 0.f, pr1 = 0.f;
        int b0 = (t * 2) * 64, b1 = (t * 2 + 1) * 64;
#pragma unroll
        for (int k = 0; k < 64; k++) {
            float hk = hreg[k];
            pl0 = fmaf(hk, swal[b0 + k], pl0);
            pl1 = fmaf(hk, swal[b1 + k], pl1);
            pr0 = fmaf(hk, swar[b0 + k], pr0);
            pr1 = fmaf(hk, swar[b1 + k], pr1);
        }
        *(float2*)&d_el[((size_t)t * NN + n) * 2] = make_float2(pl0, pl1);
        *(float2*)&d_er[((size_t)t * NN + n) * 2] = make_float2(pr0, pr1);
    }
}

// ================= segment =================
// layer 0 (fp32 x, K=23): warp-per-row, ex2 weights
__global__ void segment23_kernel(const float* __restrict__ x) {
    int tid = threadIdx.x;
    int lane = tid & 31;
    int row = (blockIdx.x * blockDim.x + tid) >> 5;
    if (row >= ROWS) return;
    int t = row / NN;
    const float* elb = d_el + (size_t)t * NN * 2;
    int beg = d_rowptr[row], end = d_rowptr[row + 1];
    float2 er2 = *(const float2*)&d_er[(size_t)row * 2];

    float den0 = 0.f, den1 = 0.f;
    float as0 = 0.f, as1 = 0.f;

    for (int j = beg; j < end; j += 2) {
        int sA = d_csrc[j];
        bool hasB = (j + 1 < end);
        int sB = hasB ? d_csrc[j + 1] : sA;
        float2 elA = *(const float2*)&elb[(size_t)sA * 2];
        float2 elB = *(const float2*)&elb[(size_t)sB * 2];
        float wA0 = wexp(elA.x + er2.x);
        float wA1 = wexp(elA.y + er2.y);
        float wB0 = hasB ? wexp(elB.x + er2.x) : 0.f;
        float wB1 = hasB ? wexp(elB.y + er2.y) : 0.f;
        den0 += wA0 + wB0;
        den1 += wA1 + wB1;
        float hA = (lane < 23) ? x[(size_t)sA * 23 + lane] : 0.f;
        float hB = (lane < 23) ? x[(size_t)sB * 23 + lane] : 0.f;
        as0 = fmaf(wA0, hA, fmaf(wB0, hB, as0));
        as1 = fmaf(wA1, hA, fmaf(wB1, hB, as1));
    }
    float inv0 = (end > beg) ? 1.f / den0 : 0.f;
    float inv1 = (end > beg) ? 1.f / den1 : 0.f;
    size_t base = (size_t)row * 48;
    if (lane < 23) {
        d_aggh[base + lane]      = __float2half(as0 * inv0);
        d_aggh[base + 24 + lane] = __float2half(as1 * inv1);
    } else if (lane == 23) {
        d_aggh[base + 23] = __float2half(0.f);
        d_aggh[base + 47] = __float2half(0.f);
    }
}

// layers 1,2 (fp16 h, K=64): TWO adjacent rows per warp (16 lanes each)
__global__ void segment64p_kernel(const __half* __restrict__ h) {
    int tid = threadIdx.x;
    int lane = tid & 31;
    int half = lane >> 4;      // row slot within warp
    int gl = lane & 15;        // lane within 16-lane group
    int widx = (blockIdx.x * blockDim.x + tid) >> 5;
    int row = widx * 2 + half;
    if (row >= ROWS) return;
    int t = row / NN;
    const float* elb = d_el + (size_t)t * NN * 2;
    const char* hb = (const char*)h;
    int beg = d_rowptr[row], end = d_rowptr[row + 1];
    float2 er2 = *(const float2*)&d_er[(size_t)row * 2];

    float den0 = 0.f, den1 = 0.f;
    float4 a0 = make_float4(0.f, 0.f, 0.f, 0.f);
    float4 a1 = make_float4(0.f, 0.f, 0.f, 0.f);

    for (int j = beg; j < end; j += 2) {
        int sA = d_csrc[j];
        bool hasB = (j + 1 < end);
        int sB = hasB ? d_csrc[j + 1] : sA;
        float2 elA = *(const float2*)&elb[(size_t)sA * 2];
        float2 elB = *(const float2*)&elb[(size_t)sB * 2];
        float wA0 = wexp(elA.x + er2.x);
        float wA1 = wexp(elA.y + er2.y);
        float wB0 = hasB ? wexp(elB.x + er2.x) : 0.f;
        float wB1 = hasB ? wexp(elB.y + er2.y) : 0.f;
        den0 += wA0 + wB0;
        den1 += wA1 + wB1;
        uint2 rA = *(const uint2*)(hb + ((size_t)sA * 128 + gl * 8));
        uint2 rB = *(const uint2*)(hb + ((size_t)sB * 128 + gl * 8));
        float2 hA0 = __half22float2(*(__half2*)&rA.x);
        float2 hA1 = __half22float2(*(__half2*)&rA.y);
        float2 hB0 = __half22float2(*(__half2*)&rB.x);
        float2 hB1 = __half22float2(*(__half2*)&rB.y);
        a0.x = fmaf(wA0, hA0.x, fmaf(wB0, hB0.x, a0.x));
        a0.y = fmaf(wA0, hA0.y, fmaf(wB0, hB0.y, a0.y));
        a0.z = fmaf(wA0, hA1.x, fmaf(wB0, hB1.x, a0.z));
        a0.w = fmaf(wA0, hA1.y, fmaf(wB0, hB1.y, a0.w));
        a1.x = fmaf(wA1, hA0.x, fmaf(wB1, hB0.x, a1.x));
        a1.y = fmaf(wA1, hA0.y, fmaf(wB1, hB0.y, a1.y));
        a1.z = fmaf(wA1, hA1.x, fmaf(wB1, hB1.x, a1.z));
        a1.w = fmaf(wA1, hA1.y, fmaf(wB1, hB1.y, a1.w));
    }
    float inv0 = (end > beg) ? 1.f / den0 : 0.f;
    float inv1 = (end > beg) ? 1.f / den1 : 0.f;
    __half2 p00 = __floats2half2_rn(a0.x * inv0, a0.y * inv0);
    __half2 p01 = __floats2half2_rn(a0.z * inv0, a0.w * inv0);
    __half2 p10 = __floats2half2_rn(a1.x * inv1, a1.y * inv1);
    __half2 p11 = __floats2half2_rn(a1.z * inv1, a1.w * inv1);
    uint2 o0, o1;
    o0.x = *(unsigned*)&p00; o0.y = *(unsigned*)&p01;
    o1.x = *(unsigned*)&p10; o1.y = *(unsigned*)&p11;
    *(uint2*)&d_aggh[(size_t)row * 128 + 4 * gl]      = o0;   // head0
    *(uint2*)&d_aggh[(size_t)row * 128 + 64 + 4 * gl] = o1;   // head1
}

// ===== out gemm 64 (layer 1): mma.sync m16n8k16 fp16 =====
__global__ void out_gemm64_kernel(const float* __restrict__ b,
                                  __half* __restrict__ hout) {
    constexpr int WS = 72;
    constexpr int AS = 136;
    __shared__ __align__(16) char sbuf[36864];
    __half* Ws = (__half*)sbuf;
    __half* As = (__half*)(sbuf + 128 * WS * 2);
    float*  St = (float*)sbuf;

    int tid = threadIdx.x;
    int warp = tid >> 5, lane = tid & 31;
    int g = lane >> 2, tg = lane & 3;
    int mrow = (warp & 3) * 16;
    int head = warp >> 2;
    int nbase = blockIdx.x * 64;
    int nvalid = min(64, NN - nbase);

    float acc[8][4];
#pragma unroll
    for (int i = 0; i < 8; i++)
#pragma unroll
        for (int j = 0; j < 4; j++) acc[i][j] = 0.f;

    for (int t = 0; t < TT; t++) {
        const uint4* wsrc = (const uint4*)(d_wt1 + (size_t)t * 128 * 64);
        for (int i = tid; i < 128 * 8; i += 256) {
            int row = i >> 3, c = i & 7;
            *(uint4*)&Ws[row * WS + c * 8] = wsrc[i];
        }
        const uint4* asrc = (const uint4*)(d_aggh + ((size_t)t * NN + nbase) * 128);
        for (int i = tid; i < nvalid * 16; i += 256) {
            int node = i >> 4, c = i & 15;
            *(uint4*)&As[node * AS + c * 8] = asrc[i];
        }
        __syncthreads();

        unsigned afr[4][4];
        const __half* Abase = As + (size_t)mrow * AS + head * 64;
#pragma unroll
        for (int k16 = 0; k16 < 4; k16++) {
            const __half* ab = Abase + k16 * 16;
            afr[k16][0] = *(const unsigned*)&ab[g * AS + tg * 2];
            afr[k16][1] = *(const unsigned*)&ab[(g + 8) * AS + tg * 2];
            afr[k16][2] = *(const unsigned*)&ab[g * AS + tg * 2 + 8];
            afr[k16][3] = *(const unsigned*)&ab[(g + 8) * AS + tg * 2 + 8];
        }
#pragma unroll
        for (int nt = 0; nt < 8; nt++) {
            const __half* wb = Ws + (size_t)(head * 64 + nt * 8 + g) * WS;
#pragma unroll
            for (int k16 = 0; k16 < 4; k16++) {
                unsigned b0 = *(const unsigned*)&wb[k16 * 16 + tg * 2];
                unsigned b1 = *(const unsigned*)&wb[k16 * 16 + tg * 2 + 8];
                MMA16816(acc[nt], afr[k16], b0, b1);
            }
        }
        __syncthreads();
    }

#pragma unroll
    for (int nt = 0; nt < 8; nt++) {
        int col = head * 64 + nt * 8 + tg * 2;
        St[(mrow + g) * 128 + col]     = acc[nt][0];
        St[(mrow + g) * 128 + col + 1] = acc[nt][1];
        St[(mrow + 8 + g) * 128 + col]     = acc[nt][2];
        St[(mrow + 8 + g) * 128 + col + 1] = acc[nt][3];
    }
    __syncthreads();

    int dd = tid & 63;
    int q = tid >> 6;
    float bm0 = 0.f, bm1 = 0.f;
#pragma unroll
    for (int t = 0; t < TT; t++) {
        bm0 += b[t * 128 + dd];
        bm1 += b[t * 128 + 64 + dd];
    }
    bm0 *= 0.25f; bm1 *= 0.25f;
#pragma unroll
    for (int i = 0; i < 16; i++) {
        int node = q * 16 + i;
        int n = nbase + node;
        if (n < NN) {
            float v0 = St[node * 128 + dd] * 0.25f + bm0;
            float v1 = St[node * 128 + 64 + dd] * 0.25f + bm1;
            v0 = fmaxf(v0, 0.f);
            v1 = fmaxf(v1, 0.f);
            float nrm = sqrtf(v0 * v0 + v1 * v1);
            float inv = 1.f / fmaxf(nrm, 1e-12f);
            hout[(size_t)n * 64 + dd] = __float2half(0.5f * (v0 + v1) * inv);
        }
    }
}

// ===== out gemm layer0 (K=23 -> padded 32): mma.sync =====
__global__ void out_gemm23_kernel(const float* __restrict__ b,
                                  __half* __restrict__ hout) {
    constexpr int WS = 40;
    constexpr int AS = 72;
    constexpr int HS = 32;
    __shared__ __align__(16) char sbuf[36864];
    __half* Ws = (__half*)sbuf;
    __half* As = (__half*)(sbuf + 128 * WS * 2);
    float*  St = (float*)sbuf;

    int tid = threadIdx.x;
    int warp = tid >> 5, lane = tid & 31;
    int g = lane >> 2, tg = lane & 3;
    int mrow = (warp & 3) * 16;
    int head = warp >> 2;
    int nbase = blockIdx.x * 64;
    int nvalid = min(64, NN - nbase);

    float acc[8][4];
#pragma unroll
    for (int i = 0; i < 8; i++)
#pragma unroll
        for (int j = 0; j < 4; j++) acc[i][j] = 0.f;

    for (int t = 0; t < TT; t++) {
        const uint4* wsrc = (const uint4*)(d_wt0 + (size_t)t * 128 * 24);
        for (int i = tid; i < 128 * 3; i += 256) {
            int row = i / 3, c = i - row * 3;
            *(uint4*)&Ws[row * WS + c * 8] = wsrc[i];
        }
        for (int i = tid; i < 128; i += 256) {
            uint4 z = make_uint4(0u, 0u, 0u, 0u);
            *(uint4*)&Ws[i * WS + 24] = z;
        }
        const __half* asrc = d_aggh + ((size_t)t * NN + nbase) * 48;
        for (int i = tid; i < nvalid * 64; i += 256) {
            int node = i >> 6, j = i & 63;
            int hh = j >> 5, k = j & 31;
            __half v = (k < 24) ? asrc[node * 48 + hh * 24 + k] : __float2half(0.f);
            As[node * AS + hh * HS + k] = v;
        }
        __syncthreads();

        unsigned afr[2][4];
        const __half* Abase = As + (size_t)mrow * AS + head * HS;
#pragma unroll
        for (int k16 = 0; k16 < 2; k16++) {
            const __half* ab = Abase + k16 * 16;
            afr[k16][0] = *(const unsigned*)&ab[g * AS + tg * 2];
            afr[k16][1] = *(const unsigned*)&ab[(g + 8) * AS + tg * 2];
            afr[k16][2] = *(const unsigned*)&ab[g * AS + tg * 2 + 8];
            afr[k16][3] = *(const unsigned*)&ab[(g + 8) * AS + tg * 2 + 8];
        }
#pragma unroll
        for (int nt = 0; nt < 8; nt++) {
            const __half* wb = Ws + (size_t)(head * 64 + nt * 8 + g) * WS;
#pragma unroll
            for (int k16 = 0; k16 < 2; k16++) {
                unsigned b0 = *(const unsigned*)&wb[k16 * 16 + tg * 2];
                unsigned b1 = *(const unsigned*)&wb[k16 * 16 + tg * 2 + 8];
                MMA16816(acc[nt], afr[k16], b0, b1);
            }
        }
        __syncthreads();
    }

#pragma unroll
    for (int nt = 0; nt < 8; nt++) {
        int col = head * 64 + nt * 8 + tg * 2;
        St[(mrow + g) * 128 + col]     = acc[nt][0];
        St[(mrow + g) * 128 + col + 1] = acc[nt][1];
        St[(mrow + 8 + g) * 128 + col]     = acc[nt][2];
        St[(mrow + 8 + g) * 128 + col + 1] = acc[nt][3];
    }
    __syncthreads();

    int dd = tid & 63;
    int q = tid >> 6;
    float bm0 = 0.f, bm1 = 0.f;
#pragma unroll
    for (int t = 0; t < TT; t++) {
        bm0 += b[t * 128 + dd];
        bm1 += b[t * 128 + 64 + dd];
    }
    bm0 *= 0.25f; bm1 *= 0.25f;
#pragma unroll
    for (int i = 0; i < 16; i++) {
        int node = q * 16 + i;
        int n = nbase + node;
        if (n < NN) {
            float v0 = St[node * 128 + dd] * 0.25f + bm0;
            float v1 = St[node * 128 + 64 + dd] * 0.25f + bm1;
            v0 = fmaxf(v0, 0.f);
            v1 = fmaxf(v1, 0.f);
            float nrm = sqrtf(v0 * v0 + v1 * v1);
            float inv = 1.f / fmaxf(nrm, 1e-12f);
            hout[(size_t)n * 64 + dd] = __float2half(0.5f * (v0 + v1) * inv);
        }
    }
}

// ==== layer 2 collapsed: node-mean of agg (half2 loads) + final GEMM ====
__global__ void aggmean_final_kernel(const float* __restrict__ W2,
                                     const float* __restrict__ b2,
                                     float* __restrict__ out) {
    int t = blockIdx.y;
    int c2 = threadIdx.x & 63;
    int sub = threadIdx.x >> 6;
    float2 s = make_float2(0.f, 0.f);
    for (int n = blockIdx.x * 2 + sub; n < NN; n += gridDim.x * 2) {
        __half2 v = *(const __half2*)&d_aggh[((size_t)t * NN + n) * 128 + 2 * c2];
        float2 f = __half22float2(v);
        s.x += f.x; s.y += f.y;
    }
    __shared__ float2 sr[128];
    sr[threadIdx.x] = s;
    __syncthreads();
    if (sub == 0) {
        float2 o = sr[c2];
        float2 o1 = sr[64 + c2];
        atomicAdd(&d_msum[t * 128 + 2 * c2],     o.x + o1.x);
        atomicAdd(&d_msum[t * 128 + 2 * c2 + 1], o.y + o1.y);
    }
    __threadfence();
    __syncthreads();
    __shared__ int flag;
    if (threadIdx.x == 0) {
        int v = atomicAdd(&d_ctr, 1);
        flag = (v == (int)(gridDim.x * gridDim.y) - 1);
    }
    __syncthreads();
    if (!flag) return;
    __threadfence();

    __shared__ float sm_m[512];
    for (int i = threadIdx.x; i < 512; i += 128) sm_m[i] = d_msum[i];
    __syncthreads();
    if (threadIdx.x < 64) {
        int dd = threadIdx.x;
        float sum = 0.f;
#pragma unroll
        for (int tt = 0; tt < TT; tt++)
#pragma unroll
            for (int hh = 0; hh < 2; hh++)
                for (int k = 0; k < 64; k++)
                    sum = fmaf(sm_m[tt * 128 + hh * 64 + k],
                               W2[((size_t)(tt * 64 + k)) * 128 + hh * 64 + dd], sum);
        sum *= 0.125f / (float)NN;
        float bb = 0.f;
#pragma unroll
        for (int tt = 0; tt < TT; tt++)
            bb += b2[tt * 128 + dd] + b2[tt * 128 + 64 + dd];
        out[dd] = sum + bb * 0.125f;
    }
}

// ================= driver =================
extern "C" void kernel_launch(void* const* d_in, const int* in_sizes, int n_in,
                              void* d_out, int out_size) {
    const float* x   = (const float*)d_in[0];
    const int* edges = (const int*)  d_in[1];
    const float* W0  = (const float*)d_in[2];
    const float* al0 = (const float*)d_in[3];
    const float* ar0 = (const float*)d_in[4];
    const float* b0  = (const float*)d_in[5];
    const float* W1  = (const float*)d_in[6];
    const float* al1 = (const float*)d_in[7];
    const float* ar1 = (const float*)d_in[8];
    const float* b1  = (const float*)d_in[9];
    const float* W2  = (const float*)d_in[10];
    const float* al2 = (const float*)d_in[11];
    const float* ar2 = (const float*)d_in[12];
    const float* b2  = (const float*)d_in[13];
    float* out = (float*)d_out;

    void* hptr = nullptr;
    cudaGetSymbolAddress(&hptr, d_hbuf);
    __half* h1 = (__half*)hptr;
    __half* h2 = h1 + (size_t)NN * 64;

    const int eg = (ETOT + 511) / 512;
    const int ng = (NN + 511) / 512;
    const int sg = (ROWS * 32 + 511) / 512;       // segment23: warp per row
    const int sgp = (ROWS / 2 * 32 + 511) / 512;  // segment64p: warp per 2 rows
    const int gg = (NN + 63) / 64;

    prep_kernel<<<256, 256>>>(W0, al0, ar0, W1, al1, ar1, W2, al2, ar2);
    hist_kernel<<<eg, 512>>>(edges);
    scanscat_eler_kernel<<<NBLK + NG23 + EG512, 512>>>(edges, x);

    // ---- layer 0 ----
    segment23_kernel<<<sg, 512>>>(x);
    out_gemm23_kernel<<<gg, 256>>>(b0, h1);

    // ---- layer 1 ----
    eler64_kernel<<<ng, 512>>>(h1, 1);
    segment64p_kernel<<<sgp, 512>>>(h1);
    out_gemm64_kernel<<<gg, 256>>>(b1, h2);

    // ---- layer 2 (collapsed output) ----
    eler64_kernel<<<ng, 512>>>(h2, 2);
    segment64p_kernel<<<sgp, 512>>>(h2);
    {
        dim3 ag(512, TT);
        aggmean_final_kernel<<<ag, 128>>>(W2, b2, out);
    }
}